// round 3
// baseline (speedup 1.0000x reference)
#include <cuda_runtime.h>

#define F  16
#define C  16
#define NB 100
#define NE 101
#define NS 102          // sbin+1 range: 0..101
#define MAXN 100000

// ---------------- device scratch (static, no allocations) ----------------
__device__ unsigned g_lo_bits[F];
__device__ unsigned g_hi_bits[F];
__device__ float    g_edges[F * NE];
__device__ int      g_counts[F * NB];
__device__ float    g_cum[F * NB];
__device__ int      g_cbin[C * F];            // [c][f], raw bins (-1..100)
__device__ unsigned char g_sbin[MAXN * F];    // sbin+1 (0..101)
__device__ float    g_G[F * NS * C];          // [f][s][c] = (sum_counts/div)^2

// ordered-uint encoding so atomicMin/Max on unsigned == float min/max
__device__ __forceinline__ unsigned fflip(float f) {
    unsigned u = __float_as_uint(f);
    return (u & 0x80000000u) ? ~u : (u | 0x80000000u);
}
__device__ __forceinline__ float funflip(unsigned u) {
    u = (u & 0x80000000u) ? (u ^ 0x80000000u) : ~u;
    return __uint_as_float(u);
}

// searchsorted over e[0..NE-1]:
//   rR = #{j : e[j] <= v}  (side='right')
//   rL = #{j : e[j] <  v}  (side='left')
// guess from affine bin width, then exact local fixup against the real edges.
__device__ __forceinline__ void search2(const float* __restrict__ e, float v,
                                        float lo, float scale, int& rR, int& rL) {
    int g = (int)((v - lo) * scale);
    g = min(max(g, 0), NE);
    while (g < NE && e[g] <= v) ++g;
    while (g > 0 && e[g - 1] > v) --g;
    rR = g;
    while (g > 0 && e[g - 1] >= v) --g;
    rL = g;
}

// ---------------- kernels ----------------
__global__ void k_init() {
    int t = threadIdx.x;
    if (t < F) { g_lo_bits[t] = 0xFFFFFFFFu; g_hi_bits[t] = 0u; }
    for (int i = t; i < F * NB; i += blockDim.x) g_counts[i] = 0;
}

__global__ void k_minmax(const float* __restrict__ z, const float* __restrict__ cl, int N) {
    int total = N + C;
    float mn[F], mx[F];
#pragma unroll
    for (int f = 0; f < F; f++) {
        mn[f] = __int_as_float(0x7f800000);   // +inf
        mx[f] = __int_as_float(0xff800000);   // -inf
    }
    for (int r = blockIdx.x * blockDim.x + threadIdx.x; r < total; r += gridDim.x * blockDim.x) {
        const float4* p = (r < N) ? (const float4*)(z + (size_t)r * F)
                                  : (const float4*)(cl + (size_t)(r - N) * F);
#pragma unroll
        for (int j = 0; j < 4; j++) {
            float4 v = p[j];
            mn[4*j+0] = fminf(mn[4*j+0], v.x); mx[4*j+0] = fmaxf(mx[4*j+0], v.x);
            mn[4*j+1] = fminf(mn[4*j+1], v.y); mx[4*j+1] = fmaxf(mx[4*j+1], v.y);
            mn[4*j+2] = fminf(mn[4*j+2], v.z); mx[4*j+2] = fmaxf(mx[4*j+2], v.z);
            mn[4*j+3] = fminf(mn[4*j+3], v.w); mx[4*j+3] = fmaxf(mx[4*j+3], v.w);
        }
    }
#pragma unroll
    for (int f = 0; f < F; f++) {
#pragma unroll
        for (int o = 16; o > 0; o >>= 1) {
            mn[f] = fminf(mn[f], __shfl_xor_sync(0xffffffffu, mn[f], o));
            mx[f] = fmaxf(mx[f], __shfl_xor_sync(0xffffffffu, mx[f], o));
        }
    }
    if ((threadIdx.x & 31) == 0) {
#pragma unroll
        for (int f = 0; f < F; f++) {
            atomicMin(&g_lo_bits[f], fflip(mn[f]));
            atomicMax(&g_hi_bits[f], fflip(mx[f]));
        }
    }
}

__global__ void k_edges_cbin(const float* __restrict__ cl) {
    int t = threadIdx.x;
    // edges[f][j] = lo + (hi-lo) * t_j,  t_j = j * (1/100) in f32, t_100 = 1
    // NO fma contraction: match XLA's separate mul + add rounding.
    for (int i = t; i < F * NE; i += blockDim.x) {
        int f = i / NE, j = i % NE;
        float lo = funflip(g_lo_bits[f]);
        float hi = funflip(g_hi_bits[f]);
        float tt = (j == NB) ? 1.0f : __fmul_rn((float)j, 0.01f);
        g_edges[i] = __fadd_rn(lo, __fmul_rn(__fsub_rn(hi, lo), tt));
    }
    __syncthreads();
    if (t < C * F) {
        int c = t / F, f = t % F;
        const float* e = &g_edges[f * NE];
        float lo = e[0], hi = e[NB];
        float scale = (hi > lo) ? (float)NB / (hi - lo) : 0.0f;
        float v = cl[c * F + f];
        int rR, rL;
        search2(e, v, lo, scale, rR, rL);
        atomicAdd(&g_counts[f * NB + min(max(rR - 1, 0), NB - 1)], 1);
        g_cbin[c * F + f] = rL - 1;
    }
}

__global__ void k_bin_z(const float* __restrict__ z, int N) {
    __shared__ float se[F * NE];
    __shared__ int   sh[F * NB];
    __shared__ float slo[F], sscale[F];
    int t = threadIdx.x, bs = blockDim.x;
    for (int i = t; i < F * NE; i += bs) se[i] = g_edges[i];
    for (int i = t; i < F * NB; i += bs) sh[i] = 0;
    if (t < F) {
        float lo = g_edges[t * NE], hi = g_edges[t * NE + NB];
        slo[t] = lo;
        sscale[t] = (hi > lo) ? (float)NB / (hi - lo) : 0.0f;
    }
    __syncthreads();
    for (int n = blockIdx.x * bs + t; n < N; n += gridDim.x * bs) {
        const float4* zp = (const float4*)(z + (size_t)n * F);
        unsigned w[4];
#pragma unroll
        for (int j = 0; j < 4; j++) {
            float4 v4 = zp[j];
            float vv[4] = {v4.x, v4.y, v4.z, v4.w};
            unsigned pk = 0;
#pragma unroll
            for (int k2 = 0; k2 < 4; k2++) {
                int f = j * 4 + k2;
                int rR, rL;
                search2(&se[f * NE], vv[k2], slo[f], sscale[f], rR, rL);
                atomicAdd(&sh[f * NB + min(max(rR - 1, 0), NB - 1)], 1);
                pk |= ((unsigned)rL) << (8 * k2);
            }
            w[j] = pk;
        }
        uint4 o; o.x = w[0]; o.y = w[1]; o.z = w[2]; o.w = w[3];
        *(uint4*)(g_sbin + (size_t)n * F) = o;
    }
    __syncthreads();
    for (int i = t; i < F * NB; i += bs) {
        int cv = sh[i];
        if (cv) atomicAdd(&g_counts[i], cv);
    }
}

__global__ void k_cum_G(float divisor) {
    int t = threadIdx.x;
    if (t < F) {
        float s = 0.0f;   // integer-valued -> exact in f32
        for (int b = 0; b < NB; b++) {
            s += (float)g_counts[t * NB + b];
            g_cum[t * NB + b] = s;
        }
    }
    __syncthreads();
    for (int i = t; i < F * NS * C; i += blockDim.x) {
        int c = i & (C - 1);
        int s = (i >> 4) % NS;
        int f = i / (NS * C);
        int sb = s - 1;
        int cb = g_cbin[c * F + f];
        int mxb = max(sb, cb), mnb = min(sb, cb);
        float hiS = g_cum[f * NB + min(max(mxb, 0), NB - 1)];
        float val = (mnb <= 0) ? hiS : (hiS - g_cum[f * NB + (mnb - 1)]);  // exact ints
        float ratio = val / divisor;   // IEEE div, matches reference
        g_G[i] = __fmul_rn(ratio, ratio);
    }
}

// thread <-> (n, c): 16 consecutive lanes share one row n (c = lane low bits)
__global__ void __launch_bounds__(512) k_main(float* __restrict__ out, int N) {
    extern __shared__ float sG[];
    int t = threadIdx.x, bs = blockDim.x;
    for (int i = t; i < (F * NS * C) / 4; i += bs)
        ((float4*)sG)[i] = ((const float4*)g_G)[i];
    __syncthreads();

    int npairs = N * C;
    int stride = gridDim.x * bs;
    for (int p0 = blockIdx.x * bs; p0 < npairs; p0 += stride) {
        int p = p0 + t;
        bool act = (p < npairs);
        int c = p & (C - 1);
        int n = min(p >> 4, N - 1);
        uint4 w = *(const uint4*)(g_sbin + (size_t)n * F);
        unsigned ww[4] = {w.x, w.y, w.z, w.w};
        float acc = 0.0f;
#pragma unroll
        for (int f = 0; f < F; f++) {
            unsigned s = (ww[f >> 2] >> (8 * (f & 3))) & 0xFFu;
            acc += sG[(f * NS + (int)s) * C + c];
        }
        float m  = sqrtf(acc);            // IEEE sqrt
        float qv = 1.0f / (1.0f + m);     // IEEE div
        float ssum = qv;
#pragma unroll
        for (int o = 1; o < 16; o <<= 1)
            ssum += __shfl_xor_sync(0xffffffffu, ssum, o);
        if (act) out[p] = qv / ssum;      // IEEE div
    }
}

// ---------------- launch ----------------
extern "C" void kernel_launch(void* const* d_in, const int* in_sizes, int n_in,
                              void* d_out, int out_size) {
    const float* z  = (const float*)d_in[0];
    const float* cl = (const float*)d_in[1];
    float* out = (float*)d_out;
    int N = in_sizes[0] / F;
    float divisor = (float)(N + C);

    static bool attr_set = false;
    // idempotent attribute set (not a stream op; capture-safe). Re-calling is harmless.
    cudaFuncSetAttribute(k_main, cudaFuncAttributeMaxDynamicSharedMemorySize,
                         F * NS * C * (int)sizeof(float));
    (void)attr_set;

    k_init<<<1, 256>>>();
    k_minmax<<<296, 256>>>(z, cl, N);
    k_edges_cbin<<<1, 256>>>(cl);
    k_bin_z<<<296, 256>>>(z, N);
    k_cum_G<<<1, 1024>>>(divisor);
    k_main<<<296, 512, F * NS * C * (int)sizeof(float)>>>(out, N);
}

// round 4
// speedup vs baseline: 1.5082x; 1.5082x over previous
#include <cuda_runtime.h>

#define F  16
#define C  16
#define NB 100
#define NE 101
#define NS 102          // sbin+1 range: 0..101
#define MAXN 100000
#define GRID1 148       // k_minmax grid (fixed; ticket pattern assumes this)

// ---------------- device scratch (static, no allocations) ----------------
__device__ float    g_part_lo[GRID1][F];
__device__ float    g_part_hi[GRID1][F];
__device__ int      g_ticket;                 // zero at load; last block resets to 0 each run
__device__ float    g_edges[F * NE];
__device__ float    g_lo[F];
__device__ float    g_scale[F];
__device__ int      g_counts[F * NB];
__device__ int      g_cbin[C * F];            // [c][f], raw bins (-1..100)
__device__ unsigned char g_sbin[MAXN * F];    // sbin+1 (0..101)

// searchsorted over e[0..NE-1]:
//   rR = #{j : e[j] <= v}  (side='right'),  rL = #{j : e[j] < v}  (side='left')
__device__ __forceinline__ void search2(const float* __restrict__ e, float v,
                                        float lo, float scale, int& rR, int& rL) {
    int g = (int)((v - lo) * scale);
    g = min(max(g, 0), NE);
    while (g < NE && e[g] <= v) ++g;
    while (g > 0 && e[g - 1] > v) --g;
    rR = g;
    while (g > 0 && e[g - 1] >= v) --g;
    rL = g;
}

// =================== K1: minmax + (last block) edges/cluster ===================
__global__ void __launch_bounds__(256) k_minmax(const float* __restrict__ z,
                                                const float* __restrict__ cl, int N) {
    int t = threadIdx.x;
    if (blockIdx.x == 0)
        for (int i = t; i < F * NB; i += 256) g_counts[i] = 0;

    float mn[F], mx[F];
#pragma unroll
    for (int f = 0; f < F; f++) {
        mn[f] = __int_as_float(0x7f800000);   // +inf
        mx[f] = __int_as_float(0xff800000);   // -inf
    }
    int total = N + C;
    for (int r = blockIdx.x * 256 + t; r < total; r += GRID1 * 256) {
        const float4* p = (r < N) ? (const float4*)(z + (size_t)r * F)
                                  : (const float4*)(cl + (size_t)(r - N) * F);
#pragma unroll
        for (int j = 0; j < 4; j++) {
            float4 v = p[j];
            mn[4*j+0] = fminf(mn[4*j+0], v.x); mx[4*j+0] = fmaxf(mx[4*j+0], v.x);
            mn[4*j+1] = fminf(mn[4*j+1], v.y); mx[4*j+1] = fmaxf(mx[4*j+1], v.y);
            mn[4*j+2] = fminf(mn[4*j+2], v.z); mx[4*j+2] = fmaxf(mx[4*j+2], v.z);
            mn[4*j+3] = fminf(mn[4*j+3], v.w); mx[4*j+3] = fmaxf(mx[4*j+3], v.w);
        }
    }
#pragma unroll
    for (int f = 0; f < F; f++) {
#pragma unroll
        for (int o = 16; o > 0; o >>= 1) {
            mn[f] = fminf(mn[f], __shfl_xor_sync(0xffffffffu, mn[f], o));
            mx[f] = fmaxf(mx[f], __shfl_xor_sync(0xffffffffu, mx[f], o));
        }
    }
    __shared__ float swlo[8][F], swhi[8][F];
    int w = t >> 5, lane = t & 31;
    if (lane == 0) {
#pragma unroll
        for (int f = 0; f < F; f++) { swlo[w][f] = mn[f]; swhi[w][f] = mx[f]; }
    }
    __syncthreads();
    if (t < F) {
        float lo = swlo[0][t], hi = swhi[0][t];
#pragma unroll
        for (int ww = 1; ww < 8; ww++) { lo = fminf(lo, swlo[ww][t]); hi = fmaxf(hi, swhi[ww][t]); }
        g_part_lo[blockIdx.x][t] = lo;
        g_part_hi[blockIdx.x][t] = hi;
    }
    __threadfence();          // every thread: publish partials (and block-0 zeroing)
    __syncthreads();
    __shared__ int sLast;
    if (t == 0) sLast = (atomicAdd(&g_ticket, 1) == GRID1 - 1);
    __syncthreads();
    if (!sLast) return;
    __threadfence();          // acquire side

    // ---- last block only: final reduce, edges, cluster bins + cluster hist ----
    __shared__ float rlo[16][F], rhi[16][F];
    {
        int f = t & 15, ch = t >> 4;   // 16 chunks x 16 features
        float lo = __int_as_float(0x7f800000), hi = __int_as_float(0xff800000);
        for (int b = ch; b < GRID1; b += 16) {
            lo = fminf(lo, __ldcg(&g_part_lo[b][f]));
            hi = fmaxf(hi, __ldcg(&g_part_hi[b][f]));
        }
        rlo[ch][f] = lo; rhi[ch][f] = hi;
    }
    __syncthreads();
    __shared__ float flo[F], fhi[F], fsc[F];
    if (t < F) {
        float lo = rlo[0][t], hi = rhi[0][t];
#pragma unroll
        for (int ch = 1; ch < 16; ch++) { lo = fminf(lo, rlo[ch][t]); hi = fmaxf(hi, rhi[ch][t]); }
        flo[t] = lo; fhi[t] = hi;
        fsc[t] = (hi > lo) ? (float)NB / (hi - lo) : 0.0f;
        g_lo[t] = lo; g_scale[t] = fsc[t];
    }
    __syncthreads();
    // edges[f][j] = lo + (hi-lo)*t_j, t_j = j*0.01f in f32 (no fma contraction)
    for (int i = t; i < F * NE; i += 256) {
        int f = i / NE, j = i % NE;
        float tt = (j == NB) ? 1.0f : __fmul_rn((float)j, 0.01f);
        g_edges[i] = __fadd_rn(flo[f], __fmul_rn(__fsub_rn(fhi[f], flo[f]), tt));
    }
    __syncthreads();
    if (t < C * F) {
        int c = t / F, f = t % F;
        int rR, rL;
        search2(&g_edges[f * NE], cl[c * F + f], flo[f], fsc[f], rR, rL);
        atomicAdd(&g_counts[f * NB + min(max(rR - 1, 0), NB - 1)], 1);
        g_cbin[t] = rL - 1;               // t == c*F + f
    }
    __threadfence();
    if (t == 0) g_ticket = 0;             // reset for next graph replay
}

// =================== K2: bin z (match-dedup per-warp u8 hist, no ATOMS) ===================
__global__ void __launch_bounds__(256) k_bin(const float* __restrict__ z, int N) {
    __shared__ float se[F * NE];
    __shared__ float slo[F], ssc[F];
    __shared__ unsigned char h8[8][F * NB];   // per-warp hist, counts <= 32 fit u8
    int t = threadIdx.x;
    for (int i = t; i < F * NE; i += 256) se[i] = g_edges[i];
    if (t < F) { slo[t] = g_lo[t]; ssc[t] = g_scale[t]; }
    for (int i = t; i < (8 * F * NB) / 4; i += 256) ((unsigned*)h8)[i] = 0u;
    __syncthreads();

    int n = blockIdx.x * 256 + t;                // one row per lane (grid covers N)
    bool valid = (n < N);
    int w = t >> 5, lane = t & 31;
    float v[F];
    if (valid) {
        const float4* zp = (const float4*)(z + (size_t)n * F);
#pragma unroll
        for (int j = 0; j < 4; j++) {
            float4 x = zp[j];
            v[4*j+0] = x.x; v[4*j+1] = x.y; v[4*j+2] = x.z; v[4*j+3] = x.w;
        }
    }
    unsigned pk[4] = {0, 0, 0, 0};
#pragma unroll
    for (int f = 0; f < F; f++) {
        int key = 127, rL = 0;
        if (valid) {
            int rR;
            search2(&se[f * NE], v[f], slo[f], ssc[f], rR, rL);
            key = min(max(rR - 1, 0), NB - 1);
        }
        unsigned mask = __match_any_sync(0xffffffffu, key);
        if (valid && lane == (__ffs(mask) - 1)) {
            int idx = f * NB + key;
            h8[w][idx] = (unsigned char)(h8[w][idx] + __popc(mask));
        }
        pk[f >> 2] |= (unsigned)rL << (8 * (f & 3));
    }
    if (valid) {
        uint4 o; o.x = pk[0]; o.y = pk[1]; o.z = pk[2]; o.w = pk[3];
        *(uint4*)(g_sbin + (size_t)n * F) = o;
    }
    __syncthreads();
    // merge 8 warp copies -> global (byte-extract, 4 bins per u32 word)
    for (int wi = t; wi < (F * NB) / 4; wi += 256) {
        unsigned s0 = 0, s1 = 0, s2 = 0, s3 = 0;
#pragma unroll
        for (int ww = 0; ww < 8; ww++) {
            unsigned x = ((const unsigned*)h8[ww])[wi];
            s0 += x & 255u; s1 += (x >> 8) & 255u; s2 += (x >> 16) & 255u; s3 += (x >> 24);
        }
        int b = wi * 4;
        if (s0) atomicAdd(&g_counts[b + 0], (int)s0);
        if (s1) atomicAdd(&g_counts[b + 1], (int)s1);
        if (s2) atomicAdd(&g_counts[b + 2], (int)s2);
        if (s3) atomicAdd(&g_counts[b + 3], (int)s3);
    }
}

// =================== K3: cum + G build (per block) + main reduction ===================
__global__ void __launch_bounds__(1024) k_main(float* __restrict__ out, int N, float divisor) {
    extern __shared__ float sG[];             // F*NS*C floats (104448 B)
    __shared__ float scum[F * NB];
    __shared__ int   scbin[C * F];
    int t = threadIdx.x;
    const int bs = 1024;

    int* stage = (int*)sG;                    // reuse sG front as count staging
    for (int i = t; i < F * NB; i += bs) stage[i] = g_counts[i];
    if (t < C * F) scbin[t] = g_cbin[t];
    __syncthreads();
    if (t < F) {
        float s = 0.0f;                       // integer-valued -> exact in f32
        for (int b = 0; b < NB; b++) { s += (float)stage[t * NB + b]; scum[t * NB + b] = s; }
    }
    __syncthreads();
    for (int i = t; i < F * NS * C; i += bs) {
        int c = i & (C - 1);
        int s = (i >> 4) % NS;                // const-div -> mul/shift
        int f = i / (NS * C);
        int sb = s - 1, cb = scbin[c * F + f];
        int mxb = max(sb, cb), mnb = min(sb, cb);
        float hiS = scum[f * NB + min(max(mxb, 0), NB - 1)];
        float val = (mnb <= 0) ? hiS : (hiS - scum[f * NB + (mnb - 1)]);  // exact ints
        float ratio = __fdiv_rn(val, divisor);
        sG[i] = __fmul_rn(ratio, ratio);
    }
    __syncthreads();

    int npairs = N * C;
    int stride = gridDim.x * bs;
    for (int p0 = blockIdx.x * bs; p0 < npairs; p0 += stride) {
        int p = p0 + t;
        bool act = (p < npairs);
        int c = p & (C - 1);
        int n = min(p >> 4, N - 1);
        uint4 wv = *(const uint4*)(g_sbin + (size_t)n * F);
        unsigned ww[4] = {wv.x, wv.y, wv.z, wv.w};
        float acc = 0.0f;
#pragma unroll
        for (int f = 0; f < F; f++) {
            unsigned s = (ww[f >> 2] >> (8 * (f & 3))) & 0xFFu;
            acc += sG[(f * NS + (int)s) * C + c];
        }
        float a2 = fmaxf(acc, 1e-30f);
        float m  = a2 * rsqrtf(a2);               // fast sqrt (MUFU.RSQ)
        float qv = __fdividef(1.0f, 1.0f + m);    // fast div
        float ssum = qv;
#pragma unroll
        for (int o = 1; o < 16; o <<= 1)
            ssum += __shfl_xor_sync(0xffffffffu, ssum, o);
        if (act) out[p] = __fdividef(qv, ssum);
    }
}

// ---------------- launch ----------------
extern "C" void kernel_launch(void* const* d_in, const int* in_sizes, int n_in,
                              void* d_out, int out_size) {
    const float* z  = (const float*)d_in[0];
    const float* cl = (const float*)d_in[1];
    float* out = (float*)d_out;
    int N = in_sizes[0] / F;
    float divisor = (float)(N + C);

    cudaFuncSetAttribute(k_main, cudaFuncAttributeMaxDynamicSharedMemorySize,
                         F * NS * C * (int)sizeof(float));

    k_minmax<<<GRID1, 256>>>(z, cl, N);
    k_bin<<<(N + 255) / 256, 256>>>(z, N);
    k_main<<<148, 1024, F * NS * C * (int)sizeof(float)>>>(out, N, divisor);
}

// round 5
// speedup vs baseline: 1.5364x; 1.0187x over previous
#include <cuda_runtime.h>

#define F  16
#define C  16
#define NB 100
#define NE 101
#define NS 102          // sbin+1 range: 0..101
#define MAXN 100000
#define GRID1 148       // k_minmax grid (fixed; ticket pattern assumes this)
#define BS1   1024

// ---------------- device scratch (static, no allocations) ----------------
__device__ float    g_part_lo[GRID1][F];
__device__ float    g_part_hi[GRID1][F];
__device__ int      g_ticket;                 // zero at load; last block resets to 0 each run
__device__ float    g_edges[F * NE];
__device__ float    g_lo[F];
__device__ float    g_scale[F];
__device__ int      g_counts[F * NB];
__device__ int      g_cbin[C * F];            // [c][f], raw bins (-1..100)
__device__ unsigned char g_sbin[MAXN * F];    // sbin+1 (0..101)

// searchsorted over e[0..NE-1]:
//   rR = #{j : e[j] <= v}  (side='right'),  rL = #{j : e[j] < v}  (side='left')
__device__ __forceinline__ void search2(const float* __restrict__ e, float v,
                                        float lo, float scale, int& rR, int& rL) {
    int g = (int)((v - lo) * scale);
    g = min(max(g, 0), NE);
    while (g < NE && e[g] <= v) ++g;
    while (g > 0 && e[g - 1] > v) --g;
    rR = g;
    while (g > 0 && e[g - 1] >= v) --g;
    rL = g;
}

// =================== K1: minmax (flat float4 stream) + (last block) edges/cluster ===================
__global__ void __launch_bounds__(BS1) k_minmax(const float* __restrict__ z,
                                                const float* __restrict__ cl, int N) {
    int t = threadIdx.x;
    if (blockIdx.x == 0)
        for (int i = t; i < F * NB; i += BS1) g_counts[i] = 0;

    const float INF = __int_as_float(0x7f800000);
    float4 mn4 = make_float4(INF, INF, INF, INF);
    float4 mx4 = make_float4(-INF, -INF, -INF, -INF);

    // flat float4 index; stride is a multiple of 4 so (i & 3) == (t & 3) forever.
    int total4 = (N + C) * 4;
    int zf4    = N * 4;
    int stride = GRID1 * BS1;
    for (int i = blockIdx.x * BS1 + t; i < total4; i += stride) {
        float4 v = (i < zf4) ? ((const float4*)z)[i] : ((const float4*)cl)[i - zf4];
        mn4.x = fminf(mn4.x, v.x); mx4.x = fmaxf(mx4.x, v.x);
        mn4.y = fminf(mn4.y, v.y); mx4.y = fmaxf(mx4.y, v.y);
        mn4.z = fminf(mn4.z, v.z); mx4.z = fmaxf(mx4.z, v.z);
        mn4.w = fminf(mn4.w, v.w); mx4.w = fmaxf(mx4.w, v.w);
    }
    // combine lanes with the same group (lane & 3)
#pragma unroll
    for (int o = 4; o < 32; o <<= 1) {
        mn4.x = fminf(mn4.x, __shfl_xor_sync(0xffffffffu, mn4.x, o));
        mn4.y = fminf(mn4.y, __shfl_xor_sync(0xffffffffu, mn4.y, o));
        mn4.z = fminf(mn4.z, __shfl_xor_sync(0xffffffffu, mn4.z, o));
        mn4.w = fminf(mn4.w, __shfl_xor_sync(0xffffffffu, mn4.w, o));
        mx4.x = fmaxf(mx4.x, __shfl_xor_sync(0xffffffffu, mx4.x, o));
        mx4.y = fmaxf(mx4.y, __shfl_xor_sync(0xffffffffu, mx4.y, o));
        mx4.z = fmaxf(mx4.z, __shfl_xor_sync(0xffffffffu, mx4.z, o));
        mx4.w = fmaxf(mx4.w, __shfl_xor_sync(0xffffffffu, mx4.w, o));
    }
    __shared__ float swlo[BS1 / 32][F], swhi[BS1 / 32][F];
    int w = t >> 5, lane = t & 31;
    if (lane < 4) {          // lane g holds features 4g..4g+3
        swlo[w][4 * lane + 0] = mn4.x; swhi[w][4 * lane + 0] = mx4.x;
        swlo[w][4 * lane + 1] = mn4.y; swhi[w][4 * lane + 1] = mx4.y;
        swlo[w][4 * lane + 2] = mn4.z; swhi[w][4 * lane + 2] = mx4.z;
        swlo[w][4 * lane + 3] = mn4.w; swhi[w][4 * lane + 3] = mx4.w;
    }
    __syncthreads();
    if (t < F) {
        float lo = swlo[0][t], hi = swhi[0][t];
#pragma unroll
        for (int ww = 1; ww < BS1 / 32; ww++) {
            lo = fminf(lo, swlo[ww][t]); hi = fmaxf(hi, swhi[ww][t]);
        }
        g_part_lo[blockIdx.x][t] = lo;
        g_part_hi[blockIdx.x][t] = hi;
    }
    __threadfence();          // publish partials (and block-0 zeroing)
    __syncthreads();
    __shared__ int sLast;
    if (t == 0) sLast = (atomicAdd(&g_ticket, 1) == GRID1 - 1);
    __syncthreads();
    if (!sLast) return;
    __threadfence();          // acquire side

    // ---- last block only: final reduce, edges, cluster bins + cluster hist ----
    __shared__ float rlo[16][F], rhi[16][F];
    if (t < 256) {
        int f = t & 15, ch = t >> 4;   // 16 chunks x 16 features
        float lo = INF, hi = -INF;
        for (int b = ch; b < GRID1; b += 16) {
            lo = fminf(lo, __ldcg(&g_part_lo[b][f]));
            hi = fmaxf(hi, __ldcg(&g_part_hi[b][f]));
        }
        rlo[ch][f] = lo; rhi[ch][f] = hi;
    }
    __syncthreads();
    __shared__ float flo[F], fhi[F], fsc[F];
    if (t < F) {
        float lo = rlo[0][t], hi = rhi[0][t];
#pragma unroll
        for (int ch = 1; ch < 16; ch++) { lo = fminf(lo, rlo[ch][t]); hi = fmaxf(hi, rhi[ch][t]); }
        flo[t] = lo; fhi[t] = hi;
        fsc[t] = (hi > lo) ? (float)NB / (hi - lo) : 0.0f;
        g_lo[t] = lo; g_scale[t] = fsc[t];
    }
    __syncthreads();
    // edges[f][j] = lo + (hi-lo)*t_j, t_j = j*0.01f in f32 (no fma contraction)
    for (int i = t; i < F * NE; i += BS1) {
        int f = i / NE, j = i % NE;
        float tt = (j == NB) ? 1.0f : __fmul_rn((float)j, 0.01f);
        g_edges[i] = __fadd_rn(flo[f], __fmul_rn(__fsub_rn(fhi[f], flo[f]), tt));
    }
    __syncthreads();
    if (t < C * F) {
        int c = t / F, f = t % F;
        int rR, rL;
        search2(&g_edges[f * NE], cl[c * F + f], flo[f], fsc[f], rR, rL);
        atomicAdd(&g_counts[f * NB + min(max(rR - 1, 0), NB - 1)], 1);
        g_cbin[t] = rL - 1;               // t == c*F + f
    }
    __threadfence();
    if (t == 0) g_ticket = 0;             // reset for next graph replay
}

// =================== K2: bin z (match-dedup per-warp u8 hist, no ATOMS) ===================
__global__ void __launch_bounds__(256) k_bin(const float* __restrict__ z, int N) {
    __shared__ float se[F * NE];
    __shared__ float slo[F], ssc[F];
    __shared__ unsigned char h8[8][F * NB];   // per-warp hist, counts <= 32 fit u8
    int t = threadIdx.x;
    for (int i = t; i < F * NE; i += 256) se[i] = g_edges[i];
    if (t < F) { slo[t] = g_lo[t]; ssc[t] = g_scale[t]; }
    for (int i = t; i < (8 * F * NB) / 4; i += 256) ((unsigned*)h8)[i] = 0u;
    __syncthreads();

    int n = blockIdx.x * 256 + t;                // one row per lane (grid covers N)
    bool valid = (n < N);
    int w = t >> 5, lane = t & 31;
    float v[F];
    if (valid) {
        const float4* zp = (const float4*)(z + (size_t)n * F);
#pragma unroll
        for (int j = 0; j < 4; j++) {
            float4 x = zp[j];
            v[4*j+0] = x.x; v[4*j+1] = x.y; v[4*j+2] = x.z; v[4*j+3] = x.w;
        }
    }
    unsigned pk[4] = {0, 0, 0, 0};
#pragma unroll
    for (int f = 0; f < F; f++) {
        int key = 127, rL = 0;
        if (valid) {
            int rR;
            search2(&se[f * NE], v[f], slo[f], ssc[f], rR, rL);
            key = min(max(rR - 1, 0), NB - 1);
        }
        unsigned mask = __match_any_sync(0xffffffffu, key);
        if (valid && lane == (__ffs(mask) - 1)) {
            int idx = f * NB + key;
            h8[w][idx] = (unsigned char)(h8[w][idx] + __popc(mask));
        }
        pk[f >> 2] |= (unsigned)rL << (8 * (f & 3));
    }
    if (valid) {
        uint4 o; o.x = pk[0]; o.y = pk[1]; o.z = pk[2]; o.w = pk[3];
        *(uint4*)(g_sbin + (size_t)n * F) = o;
    }
    __syncthreads();
    // merge 8 warp copies -> global (byte-extract, 4 bins per u32 word)
    for (int wi = t; wi < (F * NB) / 4; wi += 256) {
        unsigned s0 = 0, s1 = 0, s2 = 0, s3 = 0;
#pragma unroll
        for (int ww = 0; ww < 8; ww++) {
            unsigned x = ((const unsigned*)h8[ww])[wi];
            s0 += x & 255u; s1 += (x >> 8) & 255u; s2 += (x >> 16) & 255u; s3 += (x >> 24);
        }
        int b = wi * 4;
        if (s0) atomicAdd(&g_counts[b + 0], (int)s0);
        if (s1) atomicAdd(&g_counts[b + 1], (int)s1);
        if (s2) atomicAdd(&g_counts[b + 2], (int)s2);
        if (s3) atomicAdd(&g_counts[b + 3], (int)s3);
    }
}

// =================== K3: cum + G build (per block) + main reduction ===================
__global__ void __launch_bounds__(1024) k_main(float* __restrict__ out, int N, float divisor) {
    extern __shared__ float sG[];             // F*NS*C floats (104448 B)
    __shared__ float scum[F * NB];
    __shared__ int   scbin[C * F];
    int t = threadIdx.x;
    const int bs = 1024;

    int* stage = (int*)sG;                    // reuse sG front as count staging
    for (int i = t; i < F * NB; i += bs) stage[i] = g_counts[i];
    if (t < C * F) scbin[t] = g_cbin[t];
    __syncthreads();
    if (t < F) {
        float s = 0.0f;                       // integer-valued -> exact in f32
        for (int b = 0; b < NB; b++) { s += (float)stage[t * NB + b]; scum[t * NB + b] = s; }
    }
    __syncthreads();
    for (int i = t; i < F * NS * C; i += bs) {
        int c = i & (C - 1);
        int s = (i >> 4) % NS;                // const-div -> mul/shift
        int f = i / (NS * C);
        int sb = s - 1, cb = scbin[c * F + f];
        int mxb = max(sb, cb), mnb = min(sb, cb);
        float hiS = scum[f * NB + min(max(mxb, 0), NB - 1)];
        float val = (mnb <= 0) ? hiS : (hiS - scum[f * NB + (mnb - 1)]);  // exact ints
        float ratio = __fdiv_rn(val, divisor);
        sG[i] = __fmul_rn(ratio, ratio);
    }
    __syncthreads();

    int npairs = N * C;
    int stride = gridDim.x * bs;
    for (int p0 = blockIdx.x * bs; p0 < npairs; p0 += stride) {
        int p = p0 + t;
        bool act = (p < npairs);
        int c = p & (C - 1);
        int n = min(p >> 4, N - 1);
        uint4 wv = *(const uint4*)(g_sbin + (size_t)n * F);
        unsigned ww[4] = {wv.x, wv.y, wv.z, wv.w};
        float acc = 0.0f;
#pragma unroll
        for (int f = 0; f < F; f++) {
            unsigned s = (ww[f >> 2] >> (8 * (f & 3))) & 0xFFu;
            acc += sG[(f * NS + (int)s) * C + c];
        }
        float a2 = fmaxf(acc, 1e-30f);
        float m  = a2 * rsqrtf(a2);               // fast sqrt (MUFU.RSQ)
        float qv = __fdividef(1.0f, 1.0f + m);    // fast div
        float ssum = qv;
#pragma unroll
        for (int o = 1; o < 16; o <<= 1)
            ssum += __shfl_xor_sync(0xffffffffu, ssum, o);
        if (act) out[p] = __fdividef(qv, ssum);
    }
}

// ---------------- launch ----------------
extern "C" void kernel_launch(void* const* d_in, const int* in_sizes, int n_in,
                              void* d_out, int out_size) {
    const float* z  = (const float*)d_in[0];
    const float* cl = (const float*)d_in[1];
    float* out = (float*)d_out;
    int N = in_sizes[0] / F;
    float divisor = (float)(N + C);

    cudaFuncSetAttribute(k_main, cudaFuncAttributeMaxDynamicSharedMemorySize,
                         F * NS * C * (int)sizeof(float));

    k_minmax<<<GRID1, BS1>>>(z, cl, N);
    k_bin<<<(N + 255) / 256, 256>>>(z, N);
    k_main<<<148, 1024, F * NS * C * (int)sizeof(float)>>>(out, N, divisor);
}